// round 1
// baseline (speedup 1.0000x reference)
#include <cuda_runtime.h>
#include <cstdint>

#define B_ 4
#define S_ 2048
#define E_ 384
#define H_ 8
#define D_ 48

// ---------------- device scratch (no allocations allowed) ----------------
__device__ float g_Q[B_*H_*S_*D_];     // [B,H,S,D]
__device__ float g_K[B_*H_*S_*D_];
__device__ float g_V[B_*H_*S_*D_];
__device__ float g_attn[B_*S_*E_];     // [B,S,E] attention output (pre out-proj)
__device__ int   g_idx[B_*S_];         // per-batch compacted valid-key indices
__device__ int   g_nv[B_];             // per-batch valid-key count

#define NEG_INF (__int_as_float(0xff800000))

// ---------------------------------------------------------------------------
// Kernel 1: mask dtype detection + per-batch compaction of UNMASKED keys.
// Reference: scores = where(mask, -inf, scores)  => mask==True keys are dropped.
// One block per batch, 256 threads.
// ---------------------------------------------------------------------------
__global__ void compact_mask_kernel(const void* __restrict__ maskp) {
    const int b = blockIdx.x;
    const int t = threadIdx.x;

    // --- dtype detection: first 2048 int32 words == first 8192 bytes, safe
    // under int8 (exact buffer), int32 (first quarter) and float32 layouts.
    int okI = 1, okF = 1;
    const unsigned* mu = (const unsigned*)maskp;
    for (int i = t; i < 2048; i += 256) {
        unsigned v = mu[i];
        okI &= (v == 0u || v == 1u);
        okF &= (v == 0u || v == 0x3f800000u);
    }
    okI = __syncthreads_and(okI);
    okF = __syncthreads_and(okF);

    __shared__ int cnt[256];
    __shared__ unsigned char valid[S_];

    const int base = t * 8;
    int c = 0;
    #pragma unroll
    for (int u = 0; u < 8; ++u) {
        const int s = base + u;
        int m;
        if (okI)      m = (((const int*)maskp)[b*S_ + s] != 0);
        else if (okF) m = (((const unsigned*)maskp)[b*S_ + s] != 0u);
        else          m = (((const unsigned char*)maskp)[b*S_ + s] != 0);
        const int v = (m == 0);   // key is VALID when mask is False
        valid[s] = (unsigned char)v;
        c += v;
    }
    cnt[t] = c;
    __syncthreads();

    int pre = 0;
    for (int i = 0; i < t; ++i) pre += cnt[i];
    int off = pre;
    #pragma unroll
    for (int u = 0; u < 8; ++u) {
        const int s = base + u;
        if (valid[s]) g_idx[b*S_ + off++] = s;
    }
    if (t == 255) g_nv[b] = pre + c;
}

// ---------------------------------------------------------------------------
// Kernel 2: fused QKV projection.  C = X @ W^T + bias, written to [B,H,S,D].
// BM=BN=64, BK=16, 256 threads, 4x4 microtile. blockIdx.z selects q/k/v.
// ---------------------------------------------------------------------------
__global__ void qkv_gemm_kernel(const float* __restrict__ X,
                                const float* __restrict__ Wq, const float* __restrict__ bq,
                                const float* __restrict__ Wk, const float* __restrict__ bk,
                                const float* __restrict__ Wv, const float* __restrict__ bv) {
    const int z = blockIdx.z;
    const float* W    = (z == 0) ? Wq : (z == 1) ? Wk : Wv;
    const float* bias = (z == 0) ? bq : (z == 1) ? bk : bv;
    float* out        = (z == 0) ? g_Q : (z == 1) ? g_K : g_V;

    __shared__ float As[16][64];
    __shared__ float Bs[16][64];

    const int t  = threadIdx.x;
    const int m0 = blockIdx.x * 64;
    const int n0 = blockIdx.y * 64;

    const int lr  = t >> 2;          // 0..63 load row
    const int lc4 = (t & 3) * 4;     // 0,4,8,12 load col (float4)
    const int cm4 = (t & 15) * 4;    // microtile row base
    const int cn4 = (t >> 4) * 4;    // microtile col base

    float acc[4][4] = {};

    for (int k0 = 0; k0 < E_; k0 += 16) {
        float4 a = *(const float4*)&X[(m0 + lr) * E_ + k0 + lc4];
        float4 w = *(const float4*)&W[(n0 + lr) * E_ + k0 + lc4];
        As[lc4+0][lr] = a.x; As[lc4+1][lr] = a.y; As[lc4+2][lr] = a.z; As[lc4+3][lr] = a.w;
        Bs[lc4+0][lr] = w.x; Bs[lc4+1][lr] = w.y; Bs[lc4+2][lr] = w.z; Bs[lc4+3][lr] = w.w;
        __syncthreads();
        #pragma unroll
        for (int kk = 0; kk < 16; ++kk) {
            float av[4], bv4[4];
            *(float4*)av  = *(const float4*)&As[kk][cm4];
            *(float4*)bv4 = *(const float4*)&Bs[kk][cn4];
            #pragma unroll
            for (int i = 0; i < 4; ++i)
                #pragma unroll
                for (int j = 0; j < 4; ++j)
                    acc[i][j] = fmaf(av[i], bv4[j], acc[i][j]);
        }
        __syncthreads();
    }

    #pragma unroll
    for (int i = 0; i < 4; ++i) {
        const int m  = m0 + cm4 + i;
        const int bb = m >> 11;          // /S_
        const int s  = m & (S_ - 1);
        #pragma unroll
        for (int j = 0; j < 4; ++j) {
            const int n = n0 + cn4 + j;
            const int h = n / D_;
            const int d = n % D_;
            out[((bb * H_ + h) * S_ + s) * D_ + d] = acc[i][j] + bias[n];
        }
    }
}

// ---------------------------------------------------------------------------
// Kernel 3: flash attention over COMPACTED keys (no mask needed inside).
// Grid: (S/64, H, B). 256 threads. BQ=64, BK=64.
// smem (dynamic): Qs/Ks/Vs 64x52 (padded, float4-aligned), P 64x68.
// ---------------------------------------------------------------------------
#define QS_STRIDE 52
#define P_STRIDE  68
#define ATTN_SMEM ((3 * 64 * QS_STRIDE + 64 * P_STRIDE) * 4)   // 57344 B

__global__ void attn_kernel() {
    extern __shared__ float sm[];
    float* Qs = sm;                        // 64 x 52
    float* Ks = Qs + 64 * QS_STRIDE;       // 64 x 52
    float* Vs = Ks + 64 * QS_STRIDE;       // 64 x 52
    float* P  = Vs + 64 * QS_STRIDE;       // 64 x 68

    const int b  = blockIdx.z;
    const int h  = blockIdx.y;
    const int q0 = blockIdx.x * 64;
    const int t  = threadIdx.x;

    const float scale = 0.14433756729740643f;   // 1/sqrt(48)

    const float* Qg = g_Q + (size_t)(b * H_ + h) * S_ * D_;
    const float* Kg = g_K + (size_t)(b * H_ + h) * S_ * D_;
    const float* Vg = g_V + (size_t)(b * H_ + h) * S_ * D_;
    const int*  idxb = g_idx + b * S_;
    const int   nv   = g_nv[b];

    // load Q tile (64 x 48) once
    #pragma unroll
    for (int r = 0; r < 3; ++r) {
        const int fi  = t + r * 256;       // 0..767
        const int row = fi / 12;
        const int c4  = (fi % 12) * 4;
        float4 q4 = *(const float4*)&Qg[(q0 + row) * D_ + c4];
        *(float4*)&Qs[row * QS_STRIDE + c4] = q4;
    }

    // QK microtile mapping: 4 q-rows (contiguous) x 4 k-cols (strided by 16)
    const int qi = t >> 4;   // 0..15 -> q rows 4*qi..+3
    const int ki = t & 15;   // k cols ki + 16*j
    // softmax / PV mapping: one q-row, 12 d-columns
    const int qq = t >> 2;   // 0..63
    const int dg = t & 3;    // d slice dg*12..+11

    float m_run = NEG_INF;
    float l_run = 0.f;
    float oacc[12];
    #pragma unroll
    for (int j = 0; j < 12; ++j) oacc[j] = 0.f;

    for (int k0 = 0; k0 < nv; k0 += 64) {
        // ---- gather K/V tiles through the compaction index ----
        #pragma unroll
        for (int r = 0; r < 3; ++r) {
            const int fi  = t + r * 256;
            const int row = fi / 12;
            const int c4  = (fi % 12) * 4;
            const int kg  = k0 + row;
            float4 kk4 = make_float4(0.f, 0.f, 0.f, 0.f);
            float4 vv4 = make_float4(0.f, 0.f, 0.f, 0.f);
            if (kg < nv) {
                const int sk = idxb[kg];
                kk4 = *(const float4*)&Kg[sk * D_ + c4];
                vv4 = *(const float4*)&Vg[sk * D_ + c4];
            }
            *(float4*)&Ks[row * QS_STRIDE + c4] = kk4;
            *(float4*)&Vs[row * QS_STRIDE + c4] = vv4;
        }
        __syncthreads();

        // ---- scores: S = Q K^T ----
        float sc[4][4] = {};
        #pragma unroll
        for (int d4 = 0; d4 < D_; d4 += 4) {
            float qa[4][4], kb[4][4];
            #pragma unroll
            for (int i = 0; i < 4; ++i)
                *(float4*)qa[i] = *(const float4*)&Qs[(4 * qi + i) * QS_STRIDE + d4];
            #pragma unroll
            for (int j = 0; j < 4; ++j)
                *(float4*)kb[j] = *(const float4*)&Ks[(ki + 16 * j) * QS_STRIDE + d4];
            #pragma unroll
            for (int i = 0; i < 4; ++i)
                #pragma unroll
                for (int j = 0; j < 4; ++j) {
                    sc[i][j] = fmaf(qa[i][0], kb[j][0], sc[i][j]);
                    sc[i][j] = fmaf(qa[i][1], kb[j][1], sc[i][j]);
                    sc[i][j] = fmaf(qa[i][2], kb[j][2], sc[i][j]);
                    sc[i][j] = fmaf(qa[i][3], kb[j][3], sc[i][j]);
                }
        }
        // scale + range mask (tail of last tile), store to P
        #pragma unroll
        for (int i = 0; i < 4; ++i)
            #pragma unroll
            for (int j = 0; j < 4; ++j) {
                const int kl = ki + 16 * j;
                float v = (k0 + kl < nv) ? sc[i][j] * scale : NEG_INF;
                P[(4 * qi + i) * P_STRIDE + kl] = v;
            }
        __syncthreads();

        // ---- online softmax: 4 threads per q-row, 16 contiguous cols each ----
        float* prow = &P[qq * P_STRIDE + dg * 16];
        float vals[16];
        float mx = NEG_INF;
        #pragma unroll
        for (int i = 0; i < 16; i += 4) {
            *(float4*)&vals[i] = *(const float4*)&prow[i];
            mx = fmaxf(mx, fmaxf(fmaxf(vals[i], vals[i+1]), fmaxf(vals[i+2], vals[i+3])));
        }
        mx = fmaxf(mx, __shfl_xor_sync(0xffffffffu, mx, 1));
        mx = fmaxf(mx, __shfl_xor_sync(0xffffffffu, mx, 2));
        const float m_new = fmaxf(m_run, mx);
        float sum = 0.f;
        #pragma unroll
        for (int i = 0; i < 16; ++i) {
            vals[i] = __expf(vals[i] - m_new);
            sum += vals[i];
        }
        #pragma unroll
        for (int i = 0; i < 16; i += 4)
            *(float4*)&prow[i] = *(const float4*)&vals[i];
        sum += __shfl_xor_sync(0xffffffffu, sum, 1);
        sum += __shfl_xor_sync(0xffffffffu, sum, 2);
        const float alpha = __expf(m_run - m_new);
        l_run = l_run * alpha + sum;
        m_run = m_new;
        #pragma unroll
        for (int j = 0; j < 12; ++j) oacc[j] *= alpha;
        __syncwarp();   // P row qq written only by this quad -> warp sync suffices

        // ---- PV: oacc += P(row qq) * V ----
        #pragma unroll 4
        for (int k = 0; k < 64; k += 4) {
            float p4[4];
            *(float4*)p4 = *(const float4*)&P[qq * P_STRIDE + k];
            #pragma unroll
            for (int u = 0; u < 4; ++u) {
                const float pu = p4[u];
                const float* vb = &Vs[(k + u) * QS_STRIDE + dg * 12];
                float v0[4], v1[4], v2[4];
                *(float4*)v0 = *(const float4*)&vb[0];
                *(float4*)v1 = *(const float4*)&vb[4];
                *(float4*)v2 = *(const float4*)&vb[8];
                #pragma unroll
                for (int j = 0; j < 4; ++j) {
                    oacc[j]     = fmaf(pu, v0[j], oacc[j]);
                    oacc[j + 4] = fmaf(pu, v1[j], oacc[j + 4]);
                    oacc[j + 8] = fmaf(pu, v2[j], oacc[j + 8]);
                }
            }
        }
        __syncthreads();   // before next tile overwrites Ks/Vs
    }

    // ---- epilogue: normalize, write [B,S,E] ----
    const float inv = 1.f / l_run;
    float* op = &g_attn[(size_t)(b * S_ + q0 + qq) * E_ + h * D_ + dg * 12];
    float o0[4], o1[4], o2[4];
    #pragma unroll
    for (int j = 0; j < 4; ++j) {
        o0[j] = oacc[j] * inv;
        o1[j] = oacc[j + 4] * inv;
        o2[j] = oacc[j + 8] * inv;
    }
    *(float4*)&op[0] = *(float4*)o0;
    *(float4*)&op[4] = *(float4*)o1;
    *(float4*)&op[8] = *(float4*)o2;
}

// ---------------------------------------------------------------------------
// Kernel 4: output projection.  out = attn @ Wo^T + bo, written to d_out.
// ---------------------------------------------------------------------------
__global__ void out_gemm_kernel(const float* __restrict__ Wo,
                                const float* __restrict__ bo,
                                float* __restrict__ out) {
    __shared__ float As[16][64];
    __shared__ float Bs[16][64];

    const int t  = threadIdx.x;
    const int m0 = blockIdx.x * 64;
    const int n0 = blockIdx.y * 64;

    const int lr  = t >> 2;
    const int lc4 = (t & 3) * 4;
    const int cm4 = (t & 15) * 4;
    const int cn4 = (t >> 4) * 4;

    float acc[4][4] = {};

    for (int k0 = 0; k0 < E_; k0 += 16) {
        float4 a = *(const float4*)&g_attn[(m0 + lr) * E_ + k0 + lc4];
        float4 w = *(const float4*)&Wo[(n0 + lr) * E_ + k0 + lc4];
        As[lc4+0][lr] = a.x; As[lc4+1][lr] = a.y; As[lc4+2][lr] = a.z; As[lc4+3][lr] = a.w;
        Bs[lc4+0][lr] = w.x; Bs[lc4+1][lr] = w.y; Bs[lc4+2][lr] = w.z; Bs[lc4+3][lr] = w.w;
        __syncthreads();
        #pragma unroll
        for (int kk = 0; kk < 16; ++kk) {
            float av[4], bv4[4];
            *(float4*)av  = *(const float4*)&As[kk][cm4];
            *(float4*)bv4 = *(const float4*)&Bs[kk][cn4];
            #pragma unroll
            for (int i = 0; i < 4; ++i)
                #pragma unroll
                for (int j = 0; j < 4; ++j)
                    acc[i][j] = fmaf(av[i], bv4[j], acc[i][j]);
        }
        __syncthreads();
    }

    #pragma unroll
    for (int i = 0; i < 4; ++i) {
        const int m = m0 + cm4 + i;
        #pragma unroll
        for (int j = 0; j < 4; ++j) {
            const int n = n0 + cn4 + j;
            out[m * E_ + n] = acc[i][j] + bo[n];
        }
    }
}

// ---------------------------------------------------------------------------
extern "C" void kernel_launch(void* const* d_in, const int* in_sizes, int n_in,
                              void* d_out, int out_size) {
    const float* X    = (const float*)d_in[0];
    const void*  mask = d_in[1];
    const float* Wq   = (const float*)d_in[2];
    const float* bq   = (const float*)d_in[3];
    const float* Wk   = (const float*)d_in[4];
    const float* bk   = (const float*)d_in[5];
    const float* Wv   = (const float*)d_in[6];
    const float* bv   = (const float*)d_in[7];
    const float* Wo   = (const float*)d_in[8];
    const float* bo   = (const float*)d_in[9];
    float* out = (float*)d_out;

    cudaFuncSetAttribute(attn_kernel, cudaFuncAttributeMaxDynamicSharedMemorySize, ATTN_SMEM);

    compact_mask_kernel<<<B_, 256>>>(mask);
    qkv_gemm_kernel<<<dim3((B_*S_)/64, E_/64, 3), 256>>>(X, Wq, bq, Wk, bk, Wv, bv);
    attn_kernel<<<dim3(S_/64, H_, B_), 256, ATTN_SMEM>>>();
    out_gemm_kernel<<<dim3((B_*S_)/64, E_/64, 1), 256>>>(Wo, bo, out);
}

// round 2
// speedup vs baseline: 3.1688x; 3.1688x over previous
#include <cuda_runtime.h>
#include <cstdint>

#define B_ 4
#define S_ 2048
#define E_ 384
#define H_ 8
#define D_ 48

// ---------------- device scratch (no allocations allowed) ----------------
__device__ float g_Q[B_*H_*S_*D_];     // [B,H,S,D]
__device__ float g_K[B_*H_*S_*D_];
__device__ float g_V[B_*H_*S_*D_];
__device__ float g_attn[B_*S_*E_];     // [B,S,E] attention output (pre out-proj)
__device__ int   g_idx[B_*S_];         // per-batch compacted valid-key indices
__device__ int   g_nv[B_];             // per-batch valid-key count

#define NEG_INF (__int_as_float(0xff800000))

// ---------------- tf32 helpers ----------------
__device__ __forceinline__ unsigned f2tf(float x) {
    unsigned r;
    asm("cvt.rna.tf32.f32 %0, %1;" : "=r"(r) : "f"(x));
    return r;
}

__device__ __forceinline__ void mma_tf32(float* c,
                                         unsigned a0, unsigned a1, unsigned a2, unsigned a3,
                                         unsigned b0, unsigned b1) {
    asm volatile(
        "mma.sync.aligned.m16n8k8.row.col.f32.tf32.tf32.f32 "
        "{%0,%1,%2,%3},{%4,%5,%6,%7},{%8,%9},{%0,%1,%2,%3};"
        : "+f"(c[0]), "+f"(c[1]), "+f"(c[2]), "+f"(c[3])
        : "r"(a0), "r"(a1), "r"(a2), "r"(a3), "r"(b0), "r"(b1));
}

// ---------------------------------------------------------------------------
// Kernel 1: mask dtype detection + per-batch compaction of UNMASKED keys.
// ---------------------------------------------------------------------------
__global__ void compact_mask_kernel(const void* __restrict__ maskp) {
    const int b = blockIdx.x;
    const int t = threadIdx.x;

    int okI = 1, okF = 1;
    const unsigned* mu = (const unsigned*)maskp;
    for (int i = t; i < 2048; i += 256) {
        unsigned v = mu[i];
        okI &= (v == 0u || v == 1u);
        okF &= (v == 0u || v == 0x3f800000u);
    }
    okI = __syncthreads_and(okI);
    okF = __syncthreads_and(okF);

    __shared__ int cnt[256];
    __shared__ unsigned char valid[S_];

    const int base = t * 8;
    int c = 0;
    #pragma unroll
    for (int u = 0; u < 8; ++u) {
        const int s = base + u;
        int m;
        if (okI)      m = (((const int*)maskp)[b*S_ + s] != 0);
        else if (okF) m = (((const unsigned*)maskp)[b*S_ + s] != 0u);
        else          m = (((const unsigned char*)maskp)[b*S_ + s] != 0);
        const int v = (m == 0);   // key VALID when mask False
        valid[s] = (unsigned char)v;
        c += v;
    }
    cnt[t] = c;
    __syncthreads();

    int pre = 0;
    for (int i = 0; i < t; ++i) pre += cnt[i];
    int off = pre;
    #pragma unroll
    for (int u = 0; u < 8; ++u) {
        const int s = base + u;
        if (valid[s]) g_idx[b*S_ + off++] = s;
    }
    if (t == 255) g_nv[b] = pre + c;
}

// ---------------------------------------------------------------------------
// Kernel 2: fused QKV projection with tf32 mma.  C = X @ W^T + bias.
// BM=128, BN=64, BK=32. 256 threads = 8 warps (4m x 2n), warp tile 32x32.
// Output scattered to [B,H,S,D].
// ---------------------------------------------------------------------------
#define GST 36   // gemm smem row stride (floats)

__global__ void qkv_gemm_kernel(const float* __restrict__ X,
                                const float* __restrict__ Wq, const float* __restrict__ bq,
                                const float* __restrict__ Wk, const float* __restrict__ bk,
                                const float* __restrict__ Wv, const float* __restrict__ bv) {
    const int z = blockIdx.z;
    const float* W    = (z == 0) ? Wq : (z == 1) ? Wk : Wv;
    const float* bias = (z == 0) ? bq : (z == 1) ? bk : bv;
    float* out        = (z == 0) ? g_Q : (z == 1) ? g_K : g_V;

    __shared__ unsigned As[128 * GST];
    __shared__ unsigned Bs[64 * GST];

    const int t    = threadIdx.x;
    const int warp = t >> 5;
    const int lane = t & 31;
    const int wm   = warp & 3;      // 0..3
    const int wn   = warp >> 2;     // 0..1
    const int m0   = blockIdx.x * 128;
    const int n0   = blockIdx.y * 64;

    const int lrow = t >> 3;        // 0..31
    const int lcol = (t & 7) * 4;   // 0..28

    const int gid = lane >> 2;      // 0..7
    const int tig = lane & 3;       // 0..3

    float acc[2][4][4];
    #pragma unroll
    for (int i = 0; i < 2; ++i)
        #pragma unroll
        for (int j = 0; j < 4; ++j)
            #pragma unroll
            for (int k = 0; k < 4; ++k) acc[i][j][k] = 0.f;

    for (int k0 = 0; k0 < E_; k0 += 32) {
        #pragma unroll
        for (int r = 0; r < 4; ++r) {
            float4 a = *(const float4*)&X[(size_t)(m0 + lrow + 32*r) * E_ + k0 + lcol];
            unsigned* d = &As[(lrow + 32*r) * GST + lcol];
            d[0] = f2tf(a.x); d[1] = f2tf(a.y); d[2] = f2tf(a.z); d[3] = f2tf(a.w);
        }
        #pragma unroll
        for (int r = 0; r < 2; ++r) {
            float4 w = *(const float4*)&W[(size_t)(n0 + lrow + 32*r) * E_ + k0 + lcol];
            unsigned* d = &Bs[(lrow + 32*r) * GST + lcol];
            d[0] = f2tf(w.x); d[1] = f2tf(w.y); d[2] = f2tf(w.z); d[3] = f2tf(w.w);
        }
        __syncthreads();

        #pragma unroll
        for (int kk = 0; kk < 32; kk += 8) {
            unsigned af[2][4];
            #pragma unroll
            for (int mt = 0; mt < 2; ++mt) {
                const int mr = wm*32 + mt*16 + gid;
                af[mt][0] = As[mr * GST + kk + tig];
                af[mt][1] = As[(mr + 8) * GST + kk + tig];
                af[mt][2] = As[mr * GST + kk + 4 + tig];
                af[mt][3] = As[(mr + 8) * GST + kk + 4 + tig];
            }
            #pragma unroll
            for (int nt = 0; nt < 4; ++nt) {
                const int nr = wn*32 + nt*8 + gid;
                unsigned b0 = Bs[nr * GST + kk + tig];
                unsigned b1 = Bs[nr * GST + kk + 4 + tig];
                #pragma unroll
                for (int mt = 0; mt < 2; ++mt)
                    mma_tf32(acc[mt][nt], af[mt][0], af[mt][1], af[mt][2], af[mt][3], b0, b1);
            }
        }
        __syncthreads();
    }

    // epilogue: scatter to [B,H,S,D]
    #pragma unroll
    for (int mt = 0; mt < 2; ++mt) {
        #pragma unroll
        for (int nt = 0; nt < 4; ++nt) {
            const int m = m0 + wm*32 + mt*16 + gid;
            const int n = n0 + wn*32 + nt*8 + 2*tig;
            const float bv0 = bias[n], bv1 = bias[n+1];
            const int h = n / D_, d = n % D_;
            {
                const int bb = m >> 11, s = m & (S_ - 1);
                float2 v = make_float2(acc[mt][nt][0] + bv0, acc[mt][nt][1] + bv1);
                *(float2*)&out[((size_t)(bb * H_ + h) * S_ + s) * D_ + d] = v;
            }
            {
                const int m2 = m + 8;
                const int bb = m2 >> 11, s = m2 & (S_ - 1);
                float2 v = make_float2(acc[mt][nt][2] + bv0, acc[mt][nt][3] + bv1);
                *(float2*)&out[((size_t)(bb * H_ + h) * S_ + s) * D_ + d] = v;
            }
        }
    }
}

// ---------------------------------------------------------------------------
// Kernel 3: flash attention over COMPACTED keys, tf32 mma.
// Grid: (S/64, H, B). 128 threads = 4 warps, each warp owns 16 q-rows.
// ---------------------------------------------------------------------------
#define QS 52    // Q/K smem stride (floats)  -> conflict-free frag loads
#define VS 56    // V smem stride
#define PS 68    // P smem stride
#define ATTN_SMEM ((64*QS + 64*QS + 64*VS + 64*PS) * 4)   // 58368 B

__global__ void attn_kernel() {
    extern __shared__ unsigned sm[];
    unsigned* Qs = sm;                 // 64 x QS (tf32)
    unsigned* Ks = Qs + 64 * QS;       // 64 x QS (tf32)
    unsigned* Vs = Ks + 64 * QS;       // 64 x VS (tf32)
    unsigned* Ps = Vs + 64 * VS;       // 64 x PS (tf32)

    const int b  = blockIdx.z;
    const int h  = blockIdx.y;
    const int q0 = blockIdx.x * 64;
    const int t  = threadIdx.x;
    const int warp = t >> 5;
    const int lane = t & 31;
    const int gid  = lane >> 2;   // 0..7
    const int tig  = lane & 3;    // 0..3

    const float scale = 0.14433756729740643f;   // 1/sqrt(48)

    const float* Qg = g_Q + (size_t)(b * H_ + h) * S_ * D_;
    const float* Kg = g_K + (size_t)(b * H_ + h) * S_ * D_;
    const float* Vg = g_V + (size_t)(b * H_ + h) * S_ * D_;
    const int*  idxb = g_idx + b * S_;
    const int   nv   = g_nv[b];

    // load Q tile (64 x 48), fold in softmax scale, cvt tf32
    #pragma unroll
    for (int r = 0; r < 6; ++r) {
        const int fi  = t + r * 128;       // 0..767
        const int row = fi / 12;
        const int c4  = (fi % 12) * 4;
        float4 q4 = *(const float4*)&Qg[(size_t)(q0 + row) * D_ + c4];
        unsigned* d = &Qs[row * QS + c4];
        d[0] = f2tf(q4.x * scale); d[1] = f2tf(q4.y * scale);
        d[2] = f2tf(q4.z * scale); d[3] = f2tf(q4.w * scale);
    }

    float m0 = NEG_INF, m1 = NEG_INF;
    float l0 = 0.f, l1 = 0.f;
    float o[6][4];
    #pragma unroll
    for (int dt = 0; dt < 6; ++dt)
        #pragma unroll
        for (int j = 0; j < 4; ++j) o[dt][j] = 0.f;

    const int r0 = warp * 16 + gid;   // this thread's primary q-row in tile

    for (int k0 = 0; k0 < nv; k0 += 64) {
        // ---- gather K/V tiles through compaction index ----
        #pragma unroll
        for (int r = 0; r < 6; ++r) {
            const int fi  = t + r * 128;
            const int row = fi / 12;
            const int c4  = (fi % 12) * 4;
            const int kg  = k0 + row;
            float4 kk4 = make_float4(0.f,0.f,0.f,0.f);
            float4 vv4 = make_float4(0.f,0.f,0.f,0.f);
            if (kg < nv) {
                const int sk = idxb[kg];
                kk4 = *(const float4*)&Kg[(size_t)sk * D_ + c4];
                vv4 = *(const float4*)&Vg[(size_t)sk * D_ + c4];
            }
            unsigned* dk = &Ks[row * QS + c4];
            dk[0] = f2tf(kk4.x); dk[1] = f2tf(kk4.y); dk[2] = f2tf(kk4.z); dk[3] = f2tf(kk4.w);
            unsigned* dv = &Vs[row * VS + c4];
            dv[0] = f2tf(vv4.x); dv[1] = f2tf(vv4.y); dv[2] = f2tf(vv4.z); dv[3] = f2tf(vv4.w);
        }
        __syncthreads();

        // ---- scores: S = (Q*scale) K^T via tf32 mma; warp does 16q x 64k ----
        float sc[8][4];
        #pragma unroll
        for (int nt = 0; nt < 8; ++nt)
            #pragma unroll
            for (int j = 0; j < 4; ++j) sc[nt][j] = 0.f;

        #pragma unroll
        for (int ks = 0; ks < 6; ++ks) {
            const int kc = ks * 8;
            unsigned a0 = Qs[r0 * QS + kc + tig];
            unsigned a1 = Qs[(r0 + 8) * QS + kc + tig];
            unsigned a2 = Qs[r0 * QS + kc + 4 + tig];
            unsigned a3 = Qs[(r0 + 8) * QS + kc + 4 + tig];
            #pragma unroll
            for (int nt = 0; nt < 8; ++nt) {
                const int nr = nt*8 + gid;
                unsigned b0 = Ks[nr * QS + kc + tig];
                unsigned b1 = Ks[nr * QS + kc + 4 + tig];
                mma_tf32(sc[nt], a0, a1, a2, a3, b0, b1);
            }
        }

        // ---- tail mask (only final tile can have invalid cols) ----
        if (k0 + 64 > nv) {
            #pragma unroll
            for (int nt = 0; nt < 8; ++nt) {
                const int c0 = k0 + nt*8 + 2*tig;
                if (c0     >= nv) { sc[nt][0] = NEG_INF; sc[nt][2] = NEG_INF; }
                if (c0 + 1 >= nv) { sc[nt][1] = NEG_INF; sc[nt][3] = NEG_INF; }
            }
        }

        // ---- online softmax on fragments (rows r0 and r0+8) ----
        float mx0 = NEG_INF, mx1 = NEG_INF;
        #pragma unroll
        for (int nt = 0; nt < 8; ++nt) {
            mx0 = fmaxf(mx0, fmaxf(sc[nt][0], sc[nt][1]));
            mx1 = fmaxf(mx1, fmaxf(sc[nt][2], sc[nt][3]));
        }
        mx0 = fmaxf(mx0, __shfl_xor_sync(0xffffffffu, mx0, 1));
        mx0 = fmaxf(mx0, __shfl_xor_sync(0xffffffffu, mx0, 2));
        mx1 = fmaxf(mx1, __shfl_xor_sync(0xffffffffu, mx1, 1));
        mx1 = fmaxf(mx1, __shfl_xor_sync(0xffffffffu, mx1, 2));

        const float mn0 = fmaxf(m0, mx0);
        const float mn1 = fmaxf(m1, mx1);
        const float al0 = __expf(m0 - mn0);
        const float al1 = __expf(m1 - mn1);

        float s0 = 0.f, s1 = 0.f;
        #pragma unroll
        for (int nt = 0; nt < 8; ++nt) {
            sc[nt][0] = __expf(sc[nt][0] - mn0); s0 += sc[nt][0];
            sc[nt][1] = __expf(sc[nt][1] - mn0); s0 += sc[nt][1];
            sc[nt][2] = __expf(sc[nt][2] - mn1); s1 += sc[nt][2];
            sc[nt][3] = __expf(sc[nt][3] - mn1); s1 += sc[nt][3];
        }
        s0 += __shfl_xor_sync(0xffffffffu, s0, 1);
        s0 += __shfl_xor_sync(0xffffffffu, s0, 2);
        s1 += __shfl_xor_sync(0xffffffffu, s1, 1);
        s1 += __shfl_xor_sync(0xffffffffu, s1, 2);

        l0 = l0 * al0 + s0;  m0 = mn0;
        l1 = l1 * al1 + s1;  m1 = mn1;

        #pragma unroll
        for (int dt = 0; dt < 6; ++dt) {
            o[dt][0] *= al0; o[dt][1] *= al0;
            o[dt][2] *= al1; o[dt][3] *= al1;
        }

        // ---- store P fragments to smem (warp-private rows) ----
        #pragma unroll
        for (int nt = 0; nt < 8; ++nt) {
            const int c = nt*8 + 2*tig;
            Ps[r0 * PS + c]       = f2tf(sc[nt][0]);
            Ps[r0 * PS + c + 1]   = f2tf(sc[nt][1]);
            Ps[(r0+8) * PS + c]   = f2tf(sc[nt][2]);
            Ps[(r0+8) * PS + c+1] = f2tf(sc[nt][3]);
        }
        __syncwarp();

        // ---- O += P @ V via tf32 mma ----
        #pragma unroll
        for (int kt = 0; kt < 8; ++kt) {
            const int kc = kt * 8;
            unsigned a0 = Ps[r0 * PS + kc + tig];
            unsigned a1 = Ps[(r0 + 8) * PS + kc + tig];
            unsigned a2 = Ps[r0 * PS + kc + 4 + tig];
            unsigned a3 = Ps[(r0 + 8) * PS + kc + 4 + tig];
            #pragma unroll
            for (int dt = 0; dt < 6; ++dt) {
                unsigned b0 = Vs[(kc + tig) * VS + dt*8 + gid];
                unsigned b1 = Vs[(kc + 4 + tig) * VS + dt*8 + gid];
                mma_tf32(o[dt], a0, a1, a2, a3, b0, b1);
            }
        }
        __syncthreads();
    }

    // ---- epilogue: normalize, write to g_attn [B,S,E] ----
    const float inv0 = 1.f / l0;
    const float inv1 = 1.f / l1;
    const int qrow0 = q0 + r0;
    const int qrow1 = qrow0 + 8;
    #pragma unroll
    for (int dt = 0; dt < 6; ++dt) {
        const int dcol = h * D_ + dt*8 + 2*tig;
        *(float2*)&g_attn[(size_t)(b * S_ + qrow0) * E_ + dcol] =
            make_float2(o[dt][0] * inv0, o[dt][1] * inv0);
        *(float2*)&g_attn[(size_t)(b * S_ + qrow1) * E_ + dcol] =
            make_float2(o[dt][2] * inv1, o[dt][3] * inv1);
    }
}

// ---------------------------------------------------------------------------
// Kernel 4: output projection with tf32 mma.  out = attn @ Wo^T + bo.
// ---------------------------------------------------------------------------
__global__ void out_gemm_kernel(const float* __restrict__ Wo,
                                const float* __restrict__ bo,
                                float* __restrict__ out) {
    __shared__ unsigned As[128 * GST];
    __shared__ unsigned Bs[64 * GST];

    const int t    = threadIdx.x;
    const int warp = t >> 5;
    const int lane = t & 31;
    const int wm   = warp & 3;
    const int wn   = warp >> 2;
    const int m0   = blockIdx.x * 128;
    const int n0   = blockIdx.y * 64;

    const int lrow = t >> 3;
    const int lcol = (t & 7) * 4;

    const int gid = lane >> 2;
    const int tig = lane & 3;

    float acc[2][4][4];
    #pragma unroll
    for (int i = 0; i < 2; ++i)
        #pragma unroll
        for (int j = 0; j < 4; ++j)
            #pragma unroll
            for (int k = 0; k < 4; ++k) acc[i][j][k] = 0.f;

    for (int k0 = 0; k0 < E_; k0 += 32) {
        #pragma unroll
        for (int r = 0; r < 4; ++r) {
            float4 a = *(const float4*)&g_attn[(size_t)(m0 + lrow + 32*r) * E_ + k0 + lcol];
            unsigned* d = &As[(lrow + 32*r) * GST + lcol];
            d[0] = f2tf(a.x); d[1] = f2tf(a.y); d[2] = f2tf(a.z); d[3] = f2tf(a.w);
        }
        #pragma unroll
        for (int r = 0; r < 2; ++r) {
            float4 w = *(const float4*)&Wo[(size_t)(n0 + lrow + 32*r) * E_ + k0 + lcol];
            unsigned* d = &Bs[(lrow + 32*r) * GST + lcol];
            d[0] = f2tf(w.x); d[1] = f2tf(w.y); d[2] = f2tf(w.z); d[3] = f2tf(w.w);
        }
        __syncthreads();

        #pragma unroll
        for (int kk = 0; kk < 32; kk += 8) {
            unsigned af[2][4];
            #pragma unroll
            for (int mt = 0; mt < 2; ++mt) {
                const int mr = wm*32 + mt*16 + gid;
                af[mt][0] = As[mr * GST + kk + tig];
                af[mt][1] = As[(mr + 8) * GST + kk + tig];
                af[mt][2] = As[mr * GST + kk + 4 + tig];
                af[mt][3] = As[(mr + 8) * GST + kk + 4 + tig];
            }
            #pragma unroll
            for (int nt = 0; nt < 4; ++nt) {
                const int nr = wn*32 + nt*8 + gid;
                unsigned b0 = Bs[nr * GST + kk + tig];
                unsigned b1 = Bs[nr * GST + kk + 4 + tig];
                #pragma unroll
                for (int mt = 0; mt < 2; ++mt)
                    mma_tf32(acc[mt][nt], af[mt][0], af[mt][1], af[mt][2], af[mt][3], b0, b1);
            }
        }
        __syncthreads();
    }

    #pragma unroll
    for (int mt = 0; mt < 2; ++mt) {
        #pragma unroll
        for (int nt = 0; nt < 4; ++nt) {
            const int m = m0 + wm*32 + mt*16 + gid;
            const int n = n0 + wn*32 + nt*8 + 2*tig;
            const float bv0 = bo[n], bv1 = bo[n+1];
            *(float2*)&out[(size_t)m * E_ + n] =
                make_float2(acc[mt][nt][0] + bv0, acc[mt][nt][1] + bv1);
            *(float2*)&out[(size_t)(m + 8) * E_ + n] =
                make_float2(acc[mt][nt][2] + bv0, acc[mt][nt][3] + bv1);
        }
    }
}

// ---------------------------------------------------------------------------
extern "C" void kernel_launch(void* const* d_in, const int* in_sizes, int n_in,
                              void* d_out, int out_size) {
    const float* X    = (const float*)d_in[0];
    const void*  mask = d_in[1];
    const float* Wq   = (const float*)d_in[2];
    const float* bq   = (const float*)d_in[3];
    const float* Wk   = (const float*)d_in[4];
    const float* bk   = (const float*)d_in[5];
    const float* Wv   = (const float*)d_in[6];
    const float* bv   = (const float*)d_in[7];
    const float* Wo   = (const float*)d_in[8];
    const float* bo   = (const float*)d_in[9];
    float* out = (float*)d_out;

    cudaFuncSetAttribute(attn_kernel, cudaFuncAttributeMaxDynamicSharedMemorySize, ATTN_SMEM);

    compact_mask_kernel<<<B_, 256>>>(mask);
    qkv_gemm_kernel<<<dim3((B_*S_)/128, E_/64, 3), 256>>>(X, Wq, bq, Wk, bk, Wv, bv);
    attn_kernel<<<dim3(S_/64, H_, B_), 128, ATTN_SMEM>>>();
    out_gemm_kernel<<<dim3((B_*S_)/128, E_/64, 1), 256>>>(Wo, bo, out);
}

// round 3
// speedup vs baseline: 4.0932x; 1.2917x over previous
#include <cuda_runtime.h>
#include <cstdint>

#define B_ 4
#define S_ 2048
#define E_ 384
#define H_ 8
#define D_ 48
#define KP (S_ + 64)          // padded key pitch for compacted K/V

// ---------------- device scratch (no allocations allowed) ----------------
__device__ unsigned g_Qc[B_*H_*S_*D_];    // tf32, softmax scale folded, [B,H,S,D]
__device__ unsigned g_Kc[B_*H_*KP*D_];    // tf32, compacted keys, [B,H,KP,D]
__device__ unsigned g_Vc[B_*H_*KP*D_];    // tf32, compacted keys, [B,H,KP,D]
__device__ unsigned g_attn[B_*S_*E_];     // tf32, attention output [B,S,E]
__device__ int      g_pos[B_*S_];         // s -> compacted index, or -1
__device__ int      g_nv[B_];             // per-batch valid-key count

#define NEG_INF (__int_as_float(0xff800000))

// ---------------- tf32 helpers ----------------
__device__ __forceinline__ unsigned f2tf(float x) {
    unsigned r;
    asm("cvt.rna.tf32.f32 %0, %1;" : "=r"(r) : "f"(x));
    return r;
}

__device__ __forceinline__ void mma_tf32(float* c,
                                         unsigned a0, unsigned a1, unsigned a2, unsigned a3,
                                         unsigned b0, unsigned b1) {
    asm volatile(
        "mma.sync.aligned.m16n8k8.row.col.f32.tf32.tf32.f32 "
        "{%0,%1,%2,%3},{%4,%5,%6,%7},{%8,%9},{%0,%1,%2,%3};"
        : "+f"(c[0]), "+f"(c[1]), "+f"(c[2]), "+f"(c[3])
        : "r"(a0), "r"(a1), "r"(a2), "r"(a3), "r"(b0), "r"(b1));
}

// ---------------------------------------------------------------------------
// Kernel 1: mask dtype detection + inverse compaction map (pos) per batch.
// ---------------------------------------------------------------------------
__global__ void compact_mask_kernel(const void* __restrict__ maskp) {
    const int b = blockIdx.x;
    const int t = threadIdx.x;

    int okI = 1, okF = 1;
    const unsigned* mu = (const unsigned*)maskp;
    for (int i = t; i < 2048; i += 256) {
        unsigned v = mu[i];
        okI &= (v == 0u || v == 1u);
        okF &= (v == 0u || v == 0x3f800000u);
    }
    okI = __syncthreads_and(okI);
    okF = __syncthreads_and(okF);

    __shared__ int cnt[256];
    __shared__ unsigned char valid[S_];

    const int base = t * 8;
    int c = 0;
    #pragma unroll
    for (int u = 0; u < 8; ++u) {
        const int s = base + u;
        int m;
        if (okI)      m = (((const int*)maskp)[b*S_ + s] != 0);
        else if (okF) m = (((const unsigned*)maskp)[b*S_ + s] != 0u);
        else          m = (((const unsigned char*)maskp)[b*S_ + s] != 0);
        const int v = (m == 0);   // key VALID when mask False
        valid[s] = (unsigned char)v;
        c += v;
    }
    cnt[t] = c;
    __syncthreads();

    int pre = 0;
    for (int i = 0; i < t; ++i) pre += cnt[i];
    int off = pre;
    #pragma unroll
    for (int u = 0; u < 8; ++u) {
        const int s = base + u;
        g_pos[b*S_ + s] = valid[s] ? off : -1;
        off += valid[s];
    }
    if (t == 255) g_nv[b] = pre + c;
}

// ---------------------------------------------------------------------------
// Kernel 2: fused QKV projection (tf32 mma).  C = X @ W^T + bias.
// BM=128, BN=64, BK=32, 256 threads (8 warps, 4m x 2n), warp tile 32x32.
// Q -> g_Qc (tf32, scale folded).  K/V -> compacted tf32 via g_pos.
// ---------------------------------------------------------------------------
#define GST 36

__global__ void qkv_gemm_kernel(const float* __restrict__ X,
                                const float* __restrict__ Wq, const float* __restrict__ bq,
                                const float* __restrict__ Wk, const float* __restrict__ bk,
                                const float* __restrict__ Wv, const float* __restrict__ bv) {
    const int z = blockIdx.z;
    const float* W    = (z == 0) ? Wq : (z == 1) ? Wk : Wv;
    const float* bias = (z == 0) ? bq : (z == 1) ? bk : bv;

    __shared__ unsigned As[128 * GST];
    __shared__ unsigned Bs[64 * GST];

    const int t    = threadIdx.x;
    const int warp = t >> 5;
    const int lane = t & 31;
    const int wm   = warp & 3;
    const int wn   = warp >> 2;
    const int m0   = blockIdx.x * 128;
    const int n0   = blockIdx.y * 64;

    const int lrow = t >> 3;
    const int lcol = (t & 7) * 4;

    const int gid = lane >> 2;
    const int tig = lane & 3;

    float acc[2][4][4];
    #pragma unroll
    for (int i = 0; i < 2; ++i)
        #pragma unroll
        for (int j = 0; j < 4; ++j)
            #pragma unroll
            for (int k = 0; k < 4; ++k) acc[i][j][k] = 0.f;

    float4 pa[4], pw[2];
    #pragma unroll
    for (int r = 0; r < 4; ++r)
        pa[r] = *(const float4*)&X[(size_t)(m0 + lrow + 32*r) * E_ + lcol];
    #pragma unroll
    for (int r = 0; r < 2; ++r)
        pw[r] = *(const float4*)&W[(size_t)(n0 + lrow + 32*r) * E_ + lcol];

    for (int k0 = 0; k0 < E_; k0 += 32) {
        #pragma unroll
        for (int r = 0; r < 4; ++r) {
            unsigned* d = &As[(lrow + 32*r) * GST + lcol];
            d[0] = f2tf(pa[r].x); d[1] = f2tf(pa[r].y); d[2] = f2tf(pa[r].z); d[3] = f2tf(pa[r].w);
        }
        #pragma unroll
        for (int r = 0; r < 2; ++r) {
            unsigned* d = &Bs[(lrow + 32*r) * GST + lcol];
            d[0] = f2tf(pw[r].x); d[1] = f2tf(pw[r].y); d[2] = f2tf(pw[r].z); d[3] = f2tf(pw[r].w);
        }
        __syncthreads();

        if (k0 + 32 < E_) {
            #pragma unroll
            for (int r = 0; r < 4; ++r)
                pa[r] = *(const float4*)&X[(size_t)(m0 + lrow + 32*r) * E_ + k0 + 32 + lcol];
            #pragma unroll
            for (int r = 0; r < 2; ++r)
                pw[r] = *(const float4*)&W[(size_t)(n0 + lrow + 32*r) * E_ + k0 + 32 + lcol];
        }

        #pragma unroll
        for (int kk = 0; kk < 32; kk += 8) {
            unsigned af[2][4];
            #pragma unroll
            for (int mt = 0; mt < 2; ++mt) {
                const int mr = wm*32 + mt*16 + gid;
                af[mt][0] = As[mr * GST + kk + tig];
                af[mt][1] = As[(mr + 8) * GST + kk + tig];
                af[mt][2] = As[mr * GST + kk + 4 + tig];
                af[mt][3] = As[(mr + 8) * GST + kk + 4 + tig];
            }
            #pragma unroll
            for (int nt = 0; nt < 4; ++nt) {
                const int nr = wn*32 + nt*8 + gid;
                unsigned b0 = Bs[nr * GST + kk + tig];
                unsigned b1 = Bs[nr * GST + kk + 4 + tig];
                #pragma unroll
                for (int mt = 0; mt < 2; ++mt)
                    mma_tf32(acc[mt][nt], af[mt][0], af[mt][1], af[mt][2], af[mt][3], b0, b1);
            }
        }
        __syncthreads();
    }

    const float scale = 0.14433756729740643f;   // 1/sqrt(48), folded into Q only

    #pragma unroll
    for (int mt = 0; mt < 2; ++mt) {
        #pragma unroll
        for (int nt = 0; nt < 4; ++nt) {
            const int n = n0 + wn*32 + nt*8 + 2*tig;
            const float bv0 = bias[n], bv1 = bias[n+1];
            const int h = n / D_, d = n % D_;
            #pragma unroll
            for (int half = 0; half < 2; ++half) {
                const int m  = m0 + wm*32 + mt*16 + gid + half*8;
                const int bb = m >> 11, s = m & (S_ - 1);
                const float v0 = acc[mt][nt][2*half]     + bv0;
                const float v1 = acc[mt][nt][2*half + 1] + bv1;
                if (z == 0) {
                    uint2 u = make_uint2(f2tf(v0 * scale), f2tf(v1 * scale));
                    *(uint2*)&g_Qc[((size_t)(bb * H_ + h) * S_ + s) * D_ + d] = u;
                } else {
                    const int pos = g_pos[m];
                    if (pos >= 0) {
                        uint2 u = make_uint2(f2tf(v0), f2tf(v1));
                        unsigned* dst = (z == 1) ? g_Kc : g_Vc;
                        *(uint2*)&dst[((size_t)(bb * H_ + h) * KP + pos) * D_ + d] = u;
                    }
                }
            }
        }
    }
}

// ---------------------------------------------------------------------------
// Kernel 3: flash attention, compacted tf32 K/V, BQ=128, BK=64, 256 threads.
// Grid: (S/128, H, B). 8 warps, each owns 16 q-rows.
// ---------------------------------------------------------------------------
#define QS 52
#define VS 56
#define PS 68
#define ATTN_SMEM ((128*QS + 64*QS + 64*VS + 128*PS) * 4)   // 89088 B

__global__ void attn_kernel() {
    extern __shared__ unsigned sm[];
    unsigned* Qs = sm;                  // 128 x QS
    unsigned* Ks = Qs + 128 * QS;       // 64  x QS
    unsigned* Vs = Ks + 64 * QS;        // 64  x VS
    unsigned* Ps = Vs + 64 * VS;        // 128 x PS

    const int b  = blockIdx.z;
    const int h  = blockIdx.y;
    const int q0 = blockIdx.x * 128;
    const int t  = threadIdx.x;
    const int warp = t >> 5;
    const int lane = t & 31;
    const int gid  = lane >> 2;
    const int tig  = lane & 3;

    const unsigned* Qg = g_Qc + (size_t)(b * H_ + h) * S_ * D_;
    const unsigned* Kg = g_Kc + (size_t)(b * H_ + h) * KP * D_;
    const unsigned* Vg = g_Vc + (size_t)(b * H_ + h) * KP * D_;
    const int nv = g_nv[b];

    // load Q tile (128 x 48 tf32), raw copy
    #pragma unroll
    for (int r = 0; r < 6; ++r) {
        const int fi  = t + r * 256;       // 0..1535
        const int row = fi / 12;
        const int c4  = (fi % 12) * 4;
        *(uint4*)&Qs[row * QS + c4] = *(const uint4*)&Qg[(size_t)(q0 + row) * D_ + c4];
    }

    float m0 = NEG_INF, m1 = NEG_INF;
    float l0 = 0.f, l1 = 0.f;
    float o[6][4];
    #pragma unroll
    for (int dt = 0; dt < 6; ++dt)
        #pragma unroll
        for (int j = 0; j < 4; ++j) o[dt][j] = 0.f;

    const int r0 = warp * 16 + gid;

    // prefetch first K/V tile (rows are padded: KP = S_+64, stale data is finite)
    uint4 pk[3], pv[3];
    #pragma unroll
    for (int r = 0; r < 3; ++r) {
        const int fi  = t + r * 256;       // 0..767
        const int row = fi / 12;
        const int c4  = (fi % 12) * 4;
        pk[r] = *(const uint4*)&Kg[(size_t)row * D_ + c4];
        pv[r] = *(const uint4*)&Vg[(size_t)row * D_ + c4];
    }

    for (int k0 = 0; k0 < nv; k0 += 64) {
        #pragma unroll
        for (int r = 0; r < 3; ++r) {
            const int fi  = t + r * 256;
            const int row = fi / 12;
            const int c4  = (fi % 12) * 4;
            *(uint4*)&Ks[row * QS + c4] = pk[r];
            *(uint4*)&Vs[row * VS + c4] = pv[r];
        }
        __syncthreads();

        if (k0 + 64 < nv) {
            #pragma unroll
            for (int r = 0; r < 3; ++r) {
                const int fi  = t + r * 256;
                const int row = fi / 12;
                const int c4  = (fi % 12) * 4;
                pk[r] = *(const uint4*)&Kg[(size_t)(k0 + 64 + row) * D_ + c4];
                pv[r] = *(const uint4*)&Vg[(size_t)(k0 + 64 + row) * D_ + c4];
            }
        }

        // ---- scores: 16q x 64k per warp ----
        float sc[8][4];
        #pragma unroll
        for (int nt = 0; nt < 8; ++nt)
            #pragma unroll
            for (int j = 0; j < 4; ++j) sc[nt][j] = 0.f;

        #pragma unroll
        for (int ks = 0; ks < 6; ++ks) {
            const int kc = ks * 8;
            unsigned a0 = Qs[r0 * QS + kc + tig];
            unsigned a1 = Qs[(r0 + 8) * QS + kc + tig];
            unsigned a2 = Qs[r0 * QS + kc + 4 + tig];
            unsigned a3 = Qs[(r0 + 8) * QS + kc + 4 + tig];
            #pragma unroll
            for (int nt = 0; nt < 8; ++nt) {
                const int nr = nt*8 + gid;
                unsigned b0 = Ks[nr * QS + kc + tig];
                unsigned b1 = Ks[nr * QS + kc + 4 + tig];
                mma_tf32(sc[nt], a0, a1, a2, a3, b0, b1);
            }
        }

        // ---- tail mask ----
        if (k0 + 64 > nv) {
            #pragma unroll
            for (int nt = 0; nt < 8; ++nt) {
                const int c0 = k0 + nt*8 + 2*tig;
                if (c0     >= nv) { sc[nt][0] = NEG_INF; sc[nt][2] = NEG_INF; }
                if (c0 + 1 >= nv) { sc[nt][1] = NEG_INF; sc[nt][3] = NEG_INF; }
            }
        }

        // ---- online softmax (rows r0, r0+8) ----
        float mx0 = NEG_INF, mx1 = NEG_INF;
        #pragma unroll
        for (int nt = 0; nt < 8; ++nt) {
            mx0 = fmaxf(mx0, fmaxf(sc[nt][0], sc[nt][1]));
            mx1 = fmaxf(mx1, fmaxf(sc[nt][2], sc[nt][3]));
        }
        mx0 = fmaxf(mx0, __shfl_xor_sync(0xffffffffu, mx0, 1));
        mx0 = fmaxf(mx0, __shfl_xor_sync(0xffffffffu, mx0, 2));
        mx1 = fmaxf(mx1, __shfl_xor_sync(0xffffffffu, mx1, 1));
        mx1 = fmaxf(mx1, __shfl_xor_sync(0xffffffffu, mx1, 2));

        const float mn0 = fmaxf(m0, mx0);
        const float mn1 = fmaxf(m1, mx1);
        const float al0 = __expf(m0 - mn0);
        const float al1 = __expf(m1 - mn1);

        float s0 = 0.f, s1 = 0.f;
        #pragma unroll
        for (int nt = 0; nt < 8; ++nt) {
            sc[nt][0] = __expf(sc[nt][0] - mn0); s0 += sc[nt][0];
            sc[nt][1] = __expf(sc[nt][1] - mn0); s0 += sc[nt][1];
            sc[nt][2] = __expf(sc[nt][2] - mn1); s1 += sc[nt][2];
            sc[nt][3] = __expf(sc[nt][3] - mn1); s1 += sc[nt][3];
        }
        s0 += __shfl_xor_sync(0xffffffffu, s0, 1);
        s0 += __shfl_xor_sync(0xffffffffu, s0, 2);
        s1 += __shfl_xor_sync(0xffffffffu, s1, 1);
        s1 += __shfl_xor_sync(0xffffffffu, s1, 2);

        l0 = l0 * al0 + s0;  m0 = mn0;
        l1 = l1 * al1 + s1;  m1 = mn1;

        #pragma unroll
        for (int dt = 0; dt < 6; ++dt) {
            o[dt][0] *= al0; o[dt][1] *= al0;
            o[dt][2] *= al1; o[dt][3] *= al1;
        }

        // ---- P fragments -> smem (warp-private rows), uint2 stores ----
        #pragma unroll
        for (int nt = 0; nt < 8; ++nt) {
            const int c = nt*8 + 2*tig;
            *(uint2*)&Ps[r0 * PS + c]     = make_uint2(f2tf(sc[nt][0]), f2tf(sc[nt][1]));
            *(uint2*)&Ps[(r0+8) * PS + c] = make_uint2(f2tf(sc[nt][2]), f2tf(sc[nt][3]));
        }
        __syncwarp();

        // ---- O += P @ V ----
        #pragma unroll
        for (int kt = 0; kt < 8; ++kt) {
            const int kc = kt * 8;
            unsigned a0 = Ps[r0 * PS + kc + tig];
            unsigned a1 = Ps[(r0 + 8) * PS + kc + tig];
            unsigned a2 = Ps[r0 * PS + kc + 4 + tig];
            unsigned a3 = Ps[(r0 + 8) * PS + kc + 4 + tig];
            #pragma unroll
            for (int dt = 0; dt < 6; ++dt) {
                unsigned b0 = Vs[(kc + tig) * VS + dt*8 + gid];
                unsigned b1 = Vs[(kc + 4 + tig) * VS + dt*8 + gid];
                mma_tf32(o[dt], a0, a1, a2, a3, b0, b1);
            }
        }
        __syncthreads();
    }

    // ---- epilogue: normalize, write tf32 to g_attn [B,S,E] ----
    const float inv0 = 1.f / l0;
    const float inv1 = 1.f / l1;
    const int qrow0 = q0 + r0;
    const int qrow1 = qrow0 + 8;
    #pragma unroll
    for (int dt = 0; dt < 6; ++dt) {
        const int dcol = h * D_ + dt*8 + 2*tig;
        *(uint2*)&g_attn[(size_t)(b * S_ + qrow0) * E_ + dcol] =
            make_uint2(f2tf(o[dt][0] * inv0), f2tf(o[dt][1] * inv0));
        *(uint2*)&g_attn[(size_t)(b * S_ + qrow1) * E_ + dcol] =
            make_uint2(f2tf(o[dt][2] * inv1), f2tf(o[dt][3] * inv1));
    }
}

// ---------------------------------------------------------------------------
// Kernel 4: output projection (tf32 mma).  out = attn @ Wo^T + bo.
// A is already tf32 (raw copy); W converted on load.
// ---------------------------------------------------------------------------
__global__ void out_gemm_kernel(const float* __restrict__ Wo,
                                const float* __restrict__ bo,
                                float* __restrict__ out) {
    __shared__ unsigned As[128 * GST];
    __shared__ unsigned Bs[64 * GST];

    const int t    = threadIdx.x;
    const int warp = t >> 5;
    const int lane = t & 31;
    const int wm   = warp & 3;
    const int wn   = warp >> 2;
    const int m0   = blockIdx.x * 128;
    const int n0   = blockIdx.y * 64;

    const int lrow = t >> 3;
    const int lcol = (t & 7) * 4;

    const int gid = lane >> 2;
    const int tig = lane & 3;

    float acc[2][4][4];
    #pragma unroll
    for (int i = 0; i < 2; ++i)
        #pragma unroll
        for (int j = 0; j < 4; ++j)
            #pragma unroll
            for (int k = 0; k < 4; ++k) acc[i][j][k] = 0.f;

    uint4  pa[4];
    float4 pw[2];
    #pragma unroll
    for (int r = 0; r < 4; ++r)
        pa[r] = *(const uint4*)&g_attn[(size_t)(m0 + lrow + 32*r) * E_ + lcol];
    #pragma unroll
    for (int r = 0; r < 2; ++r)
        pw[r] = *(const float4*)&Wo[(size_t)(n0 + lrow + 32*r) * E_ + lcol];

    for (int k0 = 0; k0 < E_; k0 += 32) {
        #pragma unroll
        for (int r = 0; r < 4; ++r)
            *(uint4*)&As[(lrow + 32*r) * GST + lcol] = pa[r];
        #pragma unroll
        for (int r = 0; r < 2; ++r) {
            unsigned* d = &Bs[(lrow + 32*r) * GST + lcol];
            d[0] = f2tf(pw[r].x); d[1] = f2tf(pw[r].y); d[2] = f2tf(pw[r].z); d[3] = f2tf(pw[r].w);
        }
        __syncthreads();

        if (k0 + 32 < E_) {
            #pragma unroll
            for (int r = 0; r < 4; ++r)
                pa[r] = *(const uint4*)&g_attn[(size_t)(m0 + lrow + 32*r) * E_ + k0 + 32 + lcol];
            #pragma unroll
            for (int r = 0; r < 2; ++r)
                pw[r] = *(const float4*)&Wo[(size_t)(n0 + lrow + 32*r) * E_ + k0 + 32 + lcol];
        }

        #pragma unroll
        for (int kk = 0; kk < 32; kk += 8) {
            unsigned af[2][4];
            #pragma unroll
            for (int mt = 0; mt < 2; ++mt) {
                const int mr = wm*32 + mt*16 + gid;
                af[mt][0] = As[mr * GST + kk + tig];
                af[mt][1] = As[(mr + 8) * GST + kk + tig];
                af[mt][2] = As[mr * GST + kk + 4 + tig];
                af[mt][3] = As[(mr + 8) * GST + kk + 4 + tig];
            }
            #pragma unroll
            for (int nt = 0; nt < 4; ++nt) {
                const int nr = wn*32 + nt*8 + gid;
                unsigned b0 = Bs[nr * GST + kk + tig];
                unsigned b1 = Bs[nr * GST + kk + 4 + tig];
                #pragma unroll
                for (int mt = 0; mt < 2; ++mt)
                    mma_tf32(acc[mt][nt], af[mt][0], af[mt][1], af[mt][2], af[mt][3], b0, b1);
            }
        }
        __syncthreads();
    }

    #pragma unroll
    for (int mt = 0; mt < 2; ++mt) {
        #pragma unroll
        for (int nt = 0; nt < 4; ++nt) {
            const int m = m0 + wm*32 + mt*16 + gid;
            const int n = n0 + wn*32 + nt*8 + 2*tig;
            const float bv0 = bo[n], bv1 = bo[n+1];
            *(float2*)&out[(size_t)m * E_ + n] =
                make_float2(acc[mt][nt][0] + bv0, acc[mt][nt][1] + bv1);
            *(float2*)&out[(size_t)(m + 8) * E_ + n] =
                make_float2(acc[mt][nt][2] + bv0, acc[mt][nt][3] + bv1);
        }
    }
}

// ---------------------------------------------------------------------------
extern "C" void kernel_launch(void* const* d_in, const int* in_sizes, int n_in,
                              void* d_out, int out_size) {
    const float* X    = (const float*)d_in[0];
    const void*  mask = d_in[1];
    const float* Wq   = (const float*)d_in[2];
    const float* bq   = (const float*)d_in[3];
    const float* Wk   = (const float*)d_in[4];
    const float* bk   = (const float*)d_in[5];
    const float* Wv   = (const float*)d_in[6];
    const float* bv   = (const float*)d_in[7];
    const float* Wo   = (const float*)d_in[8];
    const float* bo   = (const float*)d_in[9];
    float* out = (float*)d_out;

    cudaFuncSetAttribute(attn_kernel, cudaFuncAttributeMaxDynamicSharedMemorySize, ATTN_SMEM);

    compact_mask_kernel<<<B_, 256>>>(mask);
    qkv_gemm_kernel<<<dim3((B_*S_)/128, E_/64, 3), 256>>>(X, Wq, bq, Wk, bk, Wv, bv);
    attn_kernel<<<dim3(S_/128, H_, B_), 256, ATTN_SMEM>>>();
    out_gemm_kernel<<<dim3((B_*S_)/128, E_/64, 1), 256>>>(Wo, bo, out);
}